// round 14
// baseline (speedup 1.0000x reference)
#include <cuda_runtime.h>

// YOLO v1 loss, S=7, B=2, C=20.
// Round 14: R6 streaming config (3 CTAs/SM, grid=3*nsm, CPB=128, NST=2
// cp.async.bulk pipeline — best measured kernel, 34.40us) with a
// minimal-tail single-node epilogue: per-CTA atomicAdd into a zero-invariant
// device scalar; last CTA atomicExch's it (restoring the invariant for graph
// replay) and stores d_out. Removes the serialized cudaMemsetAsync node
// without the multi-us read-loop tail that sank R7/R8.

#define LAMBDA_COORD 5.0f
#define LAMBDA_NOOBJ 0.5f

#define CPB      128                 // cells per tile
#define THREADS  128
#define NST      2                   // pipeline stages
#define TILE_FLOATS (CPB * 30)       // 3840 floats
#define TILE_BYTES  (TILE_FLOATS * 4)  // 15360 B

__device__ float        g_sum  = 0.0f;   // zero-invariant accumulator
__device__ unsigned int g_done = 0;      // returns to 0 every launch

// ---- PTX helpers ----
static __device__ __forceinline__ unsigned smem_u32(const void* p) {
    return (unsigned)__cvta_generic_to_shared(p);
}
static __device__ __forceinline__ void mbar_init(unsigned mbar, unsigned count) {
    asm volatile("mbarrier.init.shared.b64 [%0], %1;" :: "r"(mbar), "r"(count) : "memory");
}
static __device__ __forceinline__ void mbar_expect_tx(unsigned mbar, unsigned bytes) {
    asm volatile("mbarrier.arrive.expect_tx.shared.b64 _, [%0], %1;"
                 :: "r"(mbar), "r"(bytes) : "memory");
}
static __device__ __forceinline__ void mbar_wait(unsigned mbar, unsigned parity) {
    unsigned done;
    asm volatile(
        "{\n\t.reg .pred p;\n\t"
        "mbarrier.try_wait.parity.acquire.cta.shared::cta.b64 p, [%1], %2;\n\t"
        "selp.b32 %0, 1, 0, p;\n\t}"
        : "=r"(done) : "r"(mbar), "r"(parity) : "memory");
    while (!done) {
        asm volatile(
            "{\n\t.reg .pred p;\n\t"
            "mbarrier.try_wait.parity.acquire.cta.shared::cta.b64 p, [%1], %2, 0x989680;\n\t"
            "selp.b32 %0, 1, 0, p;\n\t}"
            : "=r"(done) : "r"(mbar), "r"(parity) : "memory");
    }
}
static __device__ __forceinline__ void bulk_g2s(unsigned dst_smem, const void* src,
                                                unsigned bytes, unsigned mbar) {
    asm volatile(
        "cp.async.bulk.shared::cluster.global.mbarrier::complete_tx::bytes [%0], [%1], %2, [%3];"
        :: "r"(dst_smem), "l"(src), "r"(bytes), "r"(mbar) : "memory");
}
static __device__ __forceinline__ void fence_proxy_async_cta() {
    asm volatile("fence.proxy.async.shared::cta;" ::: "memory");
}

// ---- per-cell loss (smem pointers, 8B-aligned) ----
static __device__ __forceinline__ float cell_loss(const float* __restrict__ p,
                                                  const float* __restrict__ l,
                                                  int n)
{
    const float INV_S = 1.0f / 7.0f;

    float2 l45 = *(const float2*)(l + 4);   // l[4]=obj (0/1)
    float obj = l45.x;

    if (obj == 0.0f) {
        float2 p45 = *(const float2*)(p + 4);
        float2 p89 = *(const float2*)(p + 8);
        float pc0 = p45.x, pc1 = p89.y;
        return LAMBDA_NOOBJ * (pc0 * pc0 + pc1 * pc1);
    }

    int within = n % 49;
    float gx = (float)(within % 7);
    float gy = (float)(within / 7);

    float2 p01 = *(const float2*)(p + 0);
    float2 p23 = *(const float2*)(p + 2);
    float2 p45 = *(const float2*)(p + 4);
    float2 p67 = *(const float2*)(p + 6);
    float2 p89 = *(const float2*)(p + 8);
    float px0 = p01.x, py0 = p01.y, pw0 = p23.x, ph0 = p23.y, pc0 = p45.x;
    float px1 = p45.y, py1 = p67.x, pw1 = p67.y, ph1 = p89.x, pc1 = p89.y;

    float2 l01 = *(const float2*)(l + 0);
    float2 l23 = *(const float2*)(l + 2);
    float lx = l01.x, ly = l01.y, lw = l23.x, lh = l23.y;

    float l_cx = (gx + lx) * INV_S, l_cy = (gy + ly) * INV_S;
    float lminx = l_cx - lw * 0.5f, lmaxx = l_cx + lw * 0.5f;
    float lminy = l_cy - lh * 0.5f, lmaxy = l_cy + lh * 0.5f;
    float area_l = lw * lh;

    float cx0 = (gx + px0) * INV_S, cy0 = (gy + py0) * INV_S;
    float iw0 = fminf(cx0 + pw0 * 0.5f, lmaxx) - fmaxf(cx0 - pw0 * 0.5f, lminx);
    float ih0 = fminf(cy0 + ph0 * 0.5f, lmaxy) - fmaxf(cy0 - ph0 * 0.5f, lminy);
    float inter0 = fmaxf(iw0, 0.0f) * fmaxf(ih0, 0.0f);
    float den0 = pw0 * ph0 + area_l - inter0 + 1e-10f;

    float cx1 = (gx + px1) * INV_S, cy1 = (gy + py1) * INV_S;
    float iw1 = fminf(cx1 + pw1 * 0.5f, lmaxx) - fmaxf(cx1 - pw1 * 0.5f, lminx);
    float ih1 = fminf(cy1 + ph1 * 0.5f, lmaxy) - fmaxf(cy1 - ph1 * 0.5f, lminy);
    float inter1 = fmaxf(iw1, 0.0f) * fmaxf(ih1, 0.0f);
    float den1 = pw1 * ph1 + area_l - inter1 + 1e-10f;

    // argmax(iou), first-wins tie-break, denominators strictly positive
    bool sel1 = (inter1 * den0) > (inter0 * den1);

    float interR = sel1 ? inter1 : inter0;
    float denR   = sel1 ? den1   : den0;
    float iouR   = __fdividef(interR, denR);

    float pxr = sel1 ? px1 : px0;
    float pyr = sel1 ? py1 : py0;
    float pwr = sel1 ? pw1 : pw0;
    float phr = sel1 ? ph1 : ph0;
    float pcr = sel1 ? pc1 : pc0;
    float pco = sel1 ? pc0 : pc1;

    float dx = pxr - lx, dy = pyr - ly;
    float wh_err = (pwr + lw - 2.0f * sqrtf(pwr * lw))
                 + (phr + lh - 2.0f * sqrtf(phr * lh));
    float dconf = pcr - iouR;

    float acc = LAMBDA_COORD * (dx * dx + dy * dy + wh_err)
              + dconf * dconf
              + LAMBDA_NOOBJ * (pco * pco);

    #pragma unroll
    for (int k = 0; k < 10; k++) {
        float2 pp = *(const float2*)(p + 10 + 2 * k);
        float2 ll = *(const float2*)(l + 10 + 2 * k);
        float d0 = pp.x - ll.x;
        float d1 = pp.y - ll.y;
        acc += d0 * d0 + d1 * d1;
    }
    return acc;
}

__global__ __launch_bounds__(THREADS, 3)
void yolo_loss_kernel(const float* __restrict__ preds,
                      const float* __restrict__ labels,
                      float* __restrict__ out,
                      int ntiles, int ncells, float inv_bs)
{
    extern __shared__ float dyn[];
    // layout: NST preds tiles, then NST labels tiles
    __shared__ __align__(8) unsigned long long mbar_store[NST];

    const int tid = threadIdx.x;

    unsigned mb[NST];
    #pragma unroll
    for (int s = 0; s < NST; s++) mb[s] = smem_u32(&mbar_store[s]);

    // producer thread inits barriers AND issues the first prefetches before
    // the block-wide sync (it needs no sync with itself).
    if (tid == 0) {
        #pragma unroll
        for (int s = 0; s < NST; s++) mbar_init(mb[s], 1);
        fence_proxy_async_cta();
        #pragma unroll
        for (int s = 0; s < NST; s++) {
            int g = blockIdx.x + s * gridDim.x;
            if (g < ntiles) {
                mbar_expect_tx(mb[s], 2 * TILE_BYTES);
                bulk_g2s(smem_u32(dyn + s * TILE_FLOATS),
                         preds + (size_t)g * TILE_FLOATS, TILE_BYTES, mb[s]);
                bulk_g2s(smem_u32(dyn + (NST + s) * TILE_FLOATS),
                         labels + (size_t)g * TILE_FLOATS, TILE_BYTES, mb[s]);
            }
        }
    }
    __syncthreads();      // consumers may now wait on the barriers

    float acc = 0.0f;
    unsigned ph = 0;          // per-stage phase bits
    int s = 0;

    for (int g = blockIdx.x; g < ntiles; g += gridDim.x) {
        mbar_wait(mb[s], (ph >> s) & 1u);
        ph ^= (1u << s);

        const float* sp = dyn + s * TILE_FLOATS + tid * 30;
        const float* sl = dyn + (NST + s) * TILE_FLOATS + tid * 30;
        acc += cell_loss(sp, sl, g * CPB + tid);

        __syncthreads();      // everyone done reading stage s

        int gn = g + NST * gridDim.x;
        if (tid == 0 && gn < ntiles) {
            mbar_expect_tx(mb[s], 2 * TILE_BYTES);
            bulk_g2s(smem_u32(dyn + s * TILE_FLOATS),
                     preds + (size_t)gn * TILE_FLOATS, TILE_BYTES, mb[s]);
            bulk_g2s(smem_u32(dyn + (NST + s) * TILE_FLOATS),
                     labels + (size_t)gn * TILE_FLOATS, TILE_BYTES, mb[s]);
        }
        s ^= 1;
    }

    // tail cells (none for this shape, but be safe)
    if (blockIdx.x == 0) {
        int c = ntiles * CPB + tid;
        if (c < ncells)
            acc += cell_loss(preds + (size_t)c * 30, labels + (size_t)c * 30, c);
    }

    // block reduction (128 threads = 4 warps)
    #pragma unroll
    for (int o = 16; o > 0; o >>= 1)
        acc += __shfl_down_sync(0xffffffffu, acc, o);

    __shared__ float wsum[THREADS / 32];
    int lane = tid & 31;
    int wid  = tid >> 5;
    if (lane == 0) wsum[wid] = acc;
    __syncthreads();

    // minimal-tail epilogue: scalar accumulator, zero-invariant across replays
    if (tid == 0) {
        float v = wsum[0] + wsum[1] + wsum[2] + wsum[3];
        atomicAdd(&g_sum, v);
        __threadfence();
        unsigned old = atomicAdd(&g_done, 1u);
        if (old == gridDim.x - 1) {
            float t = atomicExch(&g_sum, 0.0f);   // read total, restore invariant
            *out = t * inv_bs;
            g_done = 0;                           // reset for next replay
        }
    }
}

extern "C" void kernel_launch(void* const* d_in, const int* in_sizes, int n_in,
                              void* d_out, int out_size)
{
    const float* preds  = (const float*)d_in[0];
    const float* labels = (const float*)d_in[1];
    float* out = (float*)d_out;

    int ncells = in_sizes[0] / 30;          // bs * 7 * 7
    int bs     = ncells / 49;
    float inv_bs = 1.0f / (float)bs;
    int ntiles = ncells / CPB;              // 6272 full tiles for this shape

    int nsm = 148;
    cudaDeviceGetAttribute(&nsm, cudaDevAttrMultiProcessorCount, 0);

    const int smem_bytes = 2 * NST * TILE_BYTES;   // 61440 per CTA
    cudaFuncSetAttribute(yolo_loss_kernel,
                         cudaFuncAttributeMaxDynamicSharedMemorySize, smem_bytes);

    int grid = 3 * nsm;                      // R6-proven: 3 CTAs/SM
    if (grid > ntiles && ntiles > 0) grid = ntiles;
    if (grid < 1) grid = 1;

    yolo_loss_kernel<<<grid, THREADS, smem_bytes>>>(preds, labels, out,
                                                    ntiles, ncells, inv_bs);
}

// round 15
// speedup vs baseline: 1.0249x; 1.0249x over previous
#include <cuda_runtime.h>

// YOLO v1 loss, S=7, B=2, C=20.  FINAL (Round 15 = R6 consolidation).
// Persistent CTAs, 3 per SM (grid = 3*nsm), each running a 2-stage
// cp.async.bulk (1D TMA) pipeline over 128-cell tiles (15360 B per array per
// stage). Epilogue: memset node + per-CTA atomicAdd — measured cheapest of
// all epilogue variants. Best measured: 34.40us kernel, 72.5% DRAM
// (= 98% of the 192.8MB / 5.7TB/s achievable-bandwidth roofline; traffic is
// compulsory — no skippable 32B sector exists in the 120B-row layout).

#define LAMBDA_COORD 5.0f
#define LAMBDA_NOOBJ 0.5f

#define CPB      128                 // cells per tile
#define THREADS  128
#define NST      2                   // pipeline stages
#define TILE_FLOATS (CPB * 30)       // 3840 floats
#define TILE_BYTES  (TILE_FLOATS * 4)  // 15360 B

// ---- PTX helpers ----
static __device__ __forceinline__ unsigned smem_u32(const void* p) {
    return (unsigned)__cvta_generic_to_shared(p);
}
static __device__ __forceinline__ void mbar_init(unsigned mbar, unsigned count) {
    asm volatile("mbarrier.init.shared.b64 [%0], %1;" :: "r"(mbar), "r"(count) : "memory");
}
static __device__ __forceinline__ void mbar_expect_tx(unsigned mbar, unsigned bytes) {
    asm volatile("mbarrier.arrive.expect_tx.shared.b64 _, [%0], %1;"
                 :: "r"(mbar), "r"(bytes) : "memory");
}
static __device__ __forceinline__ void mbar_wait(unsigned mbar, unsigned parity) {
    unsigned done;
    asm volatile(
        "{\n\t.reg .pred p;\n\t"
        "mbarrier.try_wait.parity.acquire.cta.shared::cta.b64 p, [%1], %2;\n\t"
        "selp.b32 %0, 1, 0, p;\n\t}"
        : "=r"(done) : "r"(mbar), "r"(parity) : "memory");
    while (!done) {
        asm volatile(
            "{\n\t.reg .pred p;\n\t"
            "mbarrier.try_wait.parity.acquire.cta.shared::cta.b64 p, [%1], %2, 0x989680;\n\t"
            "selp.b32 %0, 1, 0, p;\n\t}"
            : "=r"(done) : "r"(mbar), "r"(parity) : "memory");
    }
}
static __device__ __forceinline__ void bulk_g2s(unsigned dst_smem, const void* src,
                                                unsigned bytes, unsigned mbar) {
    asm volatile(
        "cp.async.bulk.shared::cluster.global.mbarrier::complete_tx::bytes [%0], [%1], %2, [%3];"
        :: "r"(dst_smem), "l"(src), "r"(bytes), "r"(mbar) : "memory");
}
static __device__ __forceinline__ void fence_proxy_async_cta() {
    asm volatile("fence.proxy.async.shared::cta;" ::: "memory");
}

// ---- per-cell loss (smem pointers, 8B-aligned) ----
static __device__ __forceinline__ float cell_loss(const float* __restrict__ p,
                                                  const float* __restrict__ l,
                                                  int n)
{
    const float INV_S = 1.0f / 7.0f;

    float2 l45 = *(const float2*)(l + 4);   // l[4]=obj (0/1)
    float obj = l45.x;

    if (obj == 0.0f) {
        float2 p45 = *(const float2*)(p + 4);
        float2 p89 = *(const float2*)(p + 8);
        float pc0 = p45.x, pc1 = p89.y;
        return LAMBDA_NOOBJ * (pc0 * pc0 + pc1 * pc1);
    }

    int within = n % 49;
    float gx = (float)(within % 7);
    float gy = (float)(within / 7);

    float2 p01 = *(const float2*)(p + 0);
    float2 p23 = *(const float2*)(p + 2);
    float2 p45 = *(const float2*)(p + 4);
    float2 p67 = *(const float2*)(p + 6);
    float2 p89 = *(const float2*)(p + 8);
    float px0 = p01.x, py0 = p01.y, pw0 = p23.x, ph0 = p23.y, pc0 = p45.x;
    float px1 = p45.y, py1 = p67.x, pw1 = p67.y, ph1 = p89.x, pc1 = p89.y;

    float2 l01 = *(const float2*)(l + 0);
    float2 l23 = *(const float2*)(l + 2);
    float lx = l01.x, ly = l01.y, lw = l23.x, lh = l23.y;

    float l_cx = (gx + lx) * INV_S, l_cy = (gy + ly) * INV_S;
    float lminx = l_cx - lw * 0.5f, lmaxx = l_cx + lw * 0.5f;
    float lminy = l_cy - lh * 0.5f, lmaxy = l_cy + lh * 0.5f;
    float area_l = lw * lh;

    float cx0 = (gx + px0) * INV_S, cy0 = (gy + py0) * INV_S;
    float iw0 = fminf(cx0 + pw0 * 0.5f, lmaxx) - fmaxf(cx0 - pw0 * 0.5f, lminx);
    float ih0 = fminf(cy0 + ph0 * 0.5f, lmaxy) - fmaxf(cy0 - ph0 * 0.5f, lminy);
    float inter0 = fmaxf(iw0, 0.0f) * fmaxf(ih0, 0.0f);
    float den0 = pw0 * ph0 + area_l - inter0 + 1e-10f;

    float cx1 = (gx + px1) * INV_S, cy1 = (gy + py1) * INV_S;
    float iw1 = fminf(cx1 + pw1 * 0.5f, lmaxx) - fmaxf(cx1 - pw1 * 0.5f, lminx);
    float ih1 = fminf(cy1 + ph1 * 0.5f, lmaxy) - fmaxf(cy1 - ph1 * 0.5f, lminy);
    float inter1 = fmaxf(iw1, 0.0f) * fmaxf(ih1, 0.0f);
    float den1 = pw1 * ph1 + area_l - inter1 + 1e-10f;

    // argmax(iou), first-wins tie-break, denominators strictly positive
    bool sel1 = (inter1 * den0) > (inter0 * den1);

    float interR = sel1 ? inter1 : inter0;
    float denR   = sel1 ? den1   : den0;
    float iouR   = __fdividef(interR, denR);

    float pxr = sel1 ? px1 : px0;
    float pyr = sel1 ? py1 : py0;
    float pwr = sel1 ? pw1 : pw0;
    float phr = sel1 ? ph1 : ph0;
    float pcr = sel1 ? pc1 : pc0;
    float pco = sel1 ? pc0 : pc1;

    float dx = pxr - lx, dy = pyr - ly;
    float wh_err = (pwr + lw - 2.0f * sqrtf(pwr * lw))
                 + (phr + lh - 2.0f * sqrtf(phr * lh));
    float dconf = pcr - iouR;

    float acc = LAMBDA_COORD * (dx * dx + dy * dy + wh_err)
              + dconf * dconf
              + LAMBDA_NOOBJ * (pco * pco);

    #pragma unroll
    for (int k = 0; k < 10; k++) {
        float2 pp = *(const float2*)(p + 10 + 2 * k);
        float2 ll = *(const float2*)(l + 10 + 2 * k);
        float d0 = pp.x - ll.x;
        float d1 = pp.y - ll.y;
        acc += d0 * d0 + d1 * d1;
    }
    return acc;
}

__global__ __launch_bounds__(THREADS, 3)
void yolo_loss_kernel(const float* __restrict__ preds,
                      const float* __restrict__ labels,
                      float* __restrict__ out,
                      int ntiles, int ncells, float inv_bs)
{
    extern __shared__ float dyn[];
    // layout: NST preds tiles, then NST labels tiles
    __shared__ __align__(8) unsigned long long mbar_store[NST];

    const int tid = threadIdx.x;

    unsigned mb[NST];
    #pragma unroll
    for (int s = 0; s < NST; s++) mb[s] = smem_u32(&mbar_store[s]);

    if (tid == 0) {
        #pragma unroll
        for (int s = 0; s < NST; s++) mbar_init(mb[s], 1);
        fence_proxy_async_cta();
    }
    __syncthreads();

    // prefetch first NST tiles (tile g handled by CTA g % gridDim)
    if (tid == 0) {
        #pragma unroll
        for (int s = 0; s < NST; s++) {
            int g = blockIdx.x + s * gridDim.x;
            if (g < ntiles) {
                mbar_expect_tx(mb[s], 2 * TILE_BYTES);
                bulk_g2s(smem_u32(dyn + s * TILE_FLOATS),
                         preds + (size_t)g * TILE_FLOATS, TILE_BYTES, mb[s]);
                bulk_g2s(smem_u32(dyn + (NST + s) * TILE_FLOATS),
                         labels + (size_t)g * TILE_FLOATS, TILE_BYTES, mb[s]);
            }
        }
    }

    float acc = 0.0f;
    unsigned ph = 0;          // per-stage phase bits
    int s = 0;

    for (int g = blockIdx.x; g < ntiles; g += gridDim.x) {
        mbar_wait(mb[s], (ph >> s) & 1u);
        ph ^= (1u << s);

        const float* sp = dyn + s * TILE_FLOATS + tid * 30;
        const float* sl = dyn + (NST + s) * TILE_FLOATS + tid * 30;
        acc += cell_loss(sp, sl, g * CPB + tid);

        __syncthreads();      // everyone done reading stage s

        int gn = g + NST * gridDim.x;
        if (tid == 0 && gn < ntiles) {
            mbar_expect_tx(mb[s], 2 * TILE_BYTES);
            bulk_g2s(smem_u32(dyn + s * TILE_FLOATS),
                     preds + (size_t)gn * TILE_FLOATS, TILE_BYTES, mb[s]);
            bulk_g2s(smem_u32(dyn + (NST + s) * TILE_FLOATS),
                     labels + (size_t)gn * TILE_FLOATS, TILE_BYTES, mb[s]);
        }
        s ^= 1;
    }

    // tail cells (none for this shape, but be safe)
    if (blockIdx.x == 0) {
        int c = ntiles * CPB + tid;
        if (c < ncells)
            acc += cell_loss(preds + (size_t)c * 30, labels + (size_t)c * 30, c);
    }

    // block reduction (128 threads = 4 warps)
    #pragma unroll
    for (int o = 16; o > 0; o >>= 1)
        acc += __shfl_down_sync(0xffffffffu, acc, o);

    __shared__ float wsum[THREADS / 32];
    int lane = tid & 31;
    int wid  = tid >> 5;
    if (lane == 0) wsum[wid] = acc;
    __syncthreads();

    if (tid == 0) {
        float v = wsum[0] + wsum[1] + wsum[2] + wsum[3];
        atomicAdd(out, v * inv_bs);
    }
}

extern "C" void kernel_launch(void* const* d_in, const int* in_sizes, int n_in,
                              void* d_out, int out_size)
{
    const float* preds  = (const float*)d_in[0];
    const float* labels = (const float*)d_in[1];
    float* out = (float*)d_out;

    int ncells = in_sizes[0] / 30;          // bs * 7 * 7
    int bs     = ncells / 49;
    float inv_bs = 1.0f / (float)bs;
    int ntiles = ncells / CPB;              // 6272 full tiles for this shape

    int nsm = 148;
    cudaDeviceGetAttribute(&nsm, cudaDevAttrMultiProcessorCount, 0);

    const int smem_bytes = 2 * NST * TILE_BYTES;   // 61440 per CTA
    cudaFuncSetAttribute(yolo_loss_kernel,
                         cudaFuncAttributeMaxDynamicSharedMemorySize, smem_bytes);

    cudaMemsetAsync(out, 0, (size_t)out_size * sizeof(float));

    int grid = 3 * nsm;                      // 3 CTAs per SM (best measured)
    if (grid > ntiles && ntiles > 0) grid = ntiles;
    if (grid < 1) grid = 1;
    yolo_loss_kernel<<<grid, THREADS, smem_bytes>>>(preds, labels, out,
                                                    ntiles, ncells, inv_bs);
}